// round 4
// baseline (speedup 1.0000x reference)
#include <cuda_runtime.h>
#include <math.h>

#define EPSF 1e-5f

typedef unsigned long long u64;

__device__ __forceinline__ u64 pk2(float a, float b) {
    u64 r;
    asm("mov.b64 %0, {%1, %2};" : "=l"(r) : "r"(__float_as_uint(a)), "r"(__float_as_uint(b)));
    return r;
}
__device__ __forceinline__ u64 ffma2(u64 a, u64 b, u64 c) {
    u64 d;
    asm("fma.rn.f32x2 %0, %1, %2, %3;" : "=l"(d) : "l"(a), "l"(b), "l"(c));
    return d;
}
__device__ __forceinline__ void upk2(u64 v, float& lo, float& hi) {
    unsigned int l, h;
    asm("mov.b64 {%0, %1}, %2;" : "=r"(l), "=r"(h) : "l"(v));
    lo = __uint_as_float(l); hi = __uint_as_float(h);
}
__device__ __forceinline__ float gelu_f(float v) {
    return 0.5f * v * (1.0f + erff(v * 0.70710678118654752f));
}

/* intermediate: gelu(bn(involution)) result, [b=4][c=64][hw=9216] */
__device__ float g_x1[4 * 64 * 9216];

/* ================= K1: reduce + span + involution + BN + gelu ================ */
#define T1W 16
#define T1H 8
#define P1W 22
#define P1H 14
#define P1PIX (P1W * P1H)   /* 308 */

/* smem (float offsets) */
#define S1_X    0            /* 64*308 = 19712 */
#define S1_WR   19712        /* [c][16] folded reduce, 1024 */
#define S1_BR   20736        /* 16  */
#define S1_WS   20752        /* [g][r][56] span T, row-padded-8, 3584 */
#define S1_BS   24336        /* [g][56] 224 */
#define S1_SI   24560        /* 64 */
#define S1_SHI  24624        /* 64 */
#define S1_FLOATS 24688
#define S1_BYTES (S1_FLOATS * 4)   /* 98752 B -> 2 CTAs/SM */

__global__ void __launch_bounds__(256, 2)
k1_involution(const float* __restrict__ x,
              const float* __restrict__ w_reduce,
              const float* __restrict__ g_r, const float* __restrict__ b_r,
              const float* __restrict__ m_r, const float* __restrict__ v_r,
              const float* __restrict__ w_span, const float* __restrict__ b_span,
              const float* __restrict__ g_i, const float* __restrict__ b_i,
              const float* __restrict__ m_i, const float* __restrict__ v_i)
{
    extern __shared__ float sm[];
    const int tid = threadIdx.x;
    const int bb  = blockIdx.z;
    const int h0  = blockIdx.y * T1H;
    const int w0  = blockIdx.x * T1W;

    /* halo load: 64ch x 22x14 */
    {
        const int xbase = bb * 64 * 9216;
        for (int i = tid; i < 64 * P1PIX; i += 256) {
            int c  = i / P1PIX;
            int p  = i - c * P1PIX;
            int r  = p / P1W;
            int cl = p - r * P1W;
            int gh = h0 + r - 3;
            int gw = w0 + cl - 3;
            float v = 0.f;
            if ((unsigned)gh < 96u && (unsigned)gw < 96u)
                v = x[xbase + c * 9216 + gh * 96 + gw];
            sm[S1_X + i] = v;
        }
    }
    /* folded weights */
    for (int i = tid; i < 16 * 64; i += 256) {
        int c = i >> 4, r = i & 15;
        float sc = g_r[r] * rsqrtf(v_r[r] + EPSF);
        sm[S1_WR + c * 16 + r] = w_reduce[r * 64 + c] * sc;
    }
    if (tid < 16) {
        float sc = g_r[tid] * rsqrtf(v_r[tid] + EPSF);
        sm[S1_BR + tid] = b_r[tid] - m_r[tid] * sc;
    }
    for (int i = tid; i < 4 * 16 * 56; i += 256) {   /* WS[g][r][56] */
        int g = i / 896, rem = i - g * 896;
        int r = rem / 56, q = rem - r * 56;
        int row = q >> 3, j = q & 7;
        float v = (j < 7) ? w_span[(g * 49 + row * 7 + j) * 16 + r] : 0.f;
        sm[S1_WS + i] = v;
    }
    if (tid < 4 * 56) {
        int g = tid / 56, q = tid - g * 56;
        int row = q >> 3, j = q & 7;
        sm[S1_BS + tid] = (j < 7) ? b_span[g * 49 + row * 7 + j] : 0.f;
    }
    if (tid < 64) {
        float sc = g_i[tid] * rsqrtf(v_i[tid] + EPSF);
        sm[S1_SI + tid]  = sc;
        sm[S1_SHI + tid] = b_i[tid] - m_i[tid] * sc;
    }
    __syncthreads();

    const int px_id = tid & 127;
    const int gp    = tid >> 7;          /* 0/1 -> groups {0,1} or {2,3} */
    const int px    = px_id & 15;
    const int py    = px_id >> 4;
    const int cen   = (py + 3) * P1W + (px + 3);

    /* t = relu(reduce + BN), packed f32x2 */
    u64 t2[8];
    {
        const u64* br2 = (const u64*)(sm + S1_BR);
#pragma unroll
        for (int q = 0; q < 8; q++) t2[q] = br2[q];
    }
#pragma unroll 8
    for (int c = 0; c < 64; c++) {
        float xv = sm[S1_X + c * P1PIX + cen];
        u64 xv2 = pk2(xv, xv);
        const ulonglong2* w2 = (const ulonglong2*)(sm + S1_WR + c * 16);
#pragma unroll
        for (int q = 0; q < 4; q++) {
            ulonglong2 w = w2[q];
            t2[2 * q + 0] = ffma2(w.x, xv2, t2[2 * q + 0]);
            t2[2 * q + 1] = ffma2(w.y, xv2, t2[2 * q + 1]);
        }
    }
    float tt[16];
#pragma unroll
    for (int q = 0; q < 8; q++) {
        float lo, hi; upk2(t2[q], lo, hi);
        tt[2 * q] = fmaxf(lo, 0.f); tt[2 * q + 1] = fmaxf(hi, 0.f);
    }

    const int obase = bb * 64 * 9216 + (h0 + py) * 96 + (w0 + px);

#pragma unroll 1
    for (int gi = 0; gi < 2; gi++) {
        const int g = gp * 2 + gi;
        /* kern[56] (row-padded 8) */
        float kkv[56];
        {
            const float4* b4 = (const float4*)(sm + S1_BS + g * 56);
#pragma unroll
            for (int q = 0; q < 14; q++) {
                float4 b = b4[q];
                kkv[4 * q] = b.x; kkv[4 * q + 1] = b.y;
                kkv[4 * q + 2] = b.z; kkv[4 * q + 3] = b.w;
            }
        }
#pragma unroll 4
        for (int r = 0; r < 16; r++) {
            float tv = tt[r];
            const float4* w4 = (const float4*)(sm + S1_WS + (g * 16 + r) * 56);
#pragma unroll
            for (int q = 0; q < 14; q++) {
                float4 w = w4[q];
                kkv[4 * q + 0] = fmaf(w.x, tv, kkv[4 * q + 0]);
                kkv[4 * q + 1] = fmaf(w.y, tv, kkv[4 * q + 1]);
                kkv[4 * q + 2] = fmaf(w.z, tv, kkv[4 * q + 2]);
                kkv[4 * q + 3] = fmaf(w.w, tv, kkv[4 * q + 3]);
            }
        }
        /* involution over 16 channels of this group */
#pragma unroll 1
        for (int ci = 0; ci < 16; ci++) {
            const int c = g * 16 + ci;
            const float* xb = sm + S1_X + c * P1PIX + py * P1W + px;
            float a[7];
#pragma unroll
            for (int i = 0; i < 7; i++) {
                float ai = kkv[i * 8] * xb[i * P1W];
#pragma unroll
                for (int j = 1; j < 7; j++)
                    ai = fmaf(kkv[i * 8 + j], xb[i * P1W + j], ai);
                a[i] = ai;
            }
            float acc = ((a[0] + a[1]) + (a[2] + a[3])) + ((a[4] + a[5]) + a[6]);
            float v = fmaf(acc, sm[S1_SI + c], sm[S1_SHI + c]);
            g_x1[obase + c * 9216] = gelu_f(v);
        }
    }
}

/* ================= K2: fused 128x128 GEMM + bias + gelu ================ */
/* C[128 out][36864 px] = W2T . [x1 | x], tile 128 px x 128 out per CTA  */
#define S2_W   0        /* W2T[k=128][o=128] 16384 floats */
#define S2_CST 16384    /* 128 */
#define S2_FLOATS 16512
#define S2_BYTES (S2_FLOATS * 4)

__global__ void __launch_bounds__(256, 2)
k2_gemm(const float* __restrict__ x,
        const float* __restrict__ w_conv,
        const float* __restrict__ g_c, const float* __restrict__ b_c,
        const float* __restrict__ m_c, const float* __restrict__ v_c,
        const float* __restrict__ w_map, const float* __restrict__ b_map,
        const float* __restrict__ g_m, const float* __restrict__ b_m,
        const float* __restrict__ m_m, const float* __restrict__ v_m,
        float* __restrict__ out)
{
    extern __shared__ float sm[];
    const int tid = threadIdx.x;

    /* build W2T[k][o] with BN folded */
    for (int i = tid; i < 16384; i += 256) {
        int k = i >> 7, o = i & 127;
        float v;
        if (k < 64) v = w_conv[o * 64 + k]        * (g_c[o] * rsqrtf(v_c[o] + EPSF));
        else        v = w_map [o * 64 + (k - 64)] * (g_m[o] * rsqrtf(v_m[o] + EPSF));
        sm[S2_W + i] = v;
    }
    if (tid < 128) {
        float sc_c = g_c[tid] * rsqrtf(v_c[tid] + EPSF);
        float sc_m = g_m[tid] * rsqrtf(v_m[tid] + EPSF);
        sm[S2_CST + tid] = (b_c[tid] - m_c[tid] * sc_c)
                         + sc_m * b_map[tid]
                         + (b_m[tid] - m_m[tid] * sc_m);
    }
    __syncthreads();

    const int P0  = blockIdx.x * 128;        /* global pixel base */
    const int b   = P0 / 9216;
    const int off = P0 - b * 9216;
    const int px_t  = tid & 15;              /* 8 px each  */
    const int out_t = tid >> 4;              /* 8 out each */

    u64 acc[32];                             /* [oo=8][pp=4] px pairs */
#pragma unroll
    for (int q = 0; q < 32; q++) acc[q] = 0ULL;

    const float* ybase[2];
    ybase[0] = g_x1 + (b * 64) * 9216 + off + px_t * 8;
    ybase[1] = x    + (b * 64) * 9216 + off + px_t * 8;

#pragma unroll 1
    for (int half = 0; half < 2; half++) {
        const float* yb = ybase[half];
        const float* wb = sm + S2_W + (half * 64) * 128 + out_t * 8;
#pragma unroll 4
        for (int k = 0; k < 64; k++) {
            const ulonglong2* yp = (const ulonglong2*)(yb + k * 9216);
            ulonglong2 y0 = yp[0];
            ulonglong2 y1 = yp[1];
            const float4* wp = (const float4*)(wb + k * 128);
            float4 w0 = wp[0];
            float4 w1 = wp[1];
            float wv[8] = {w0.x, w0.y, w0.z, w0.w, w1.x, w1.y, w1.z, w1.w};
#pragma unroll
            for (int oo = 0; oo < 8; oo++) {
                u64 wq = pk2(wv[oo], wv[oo]);
                acc[oo * 4 + 0] = ffma2(wq, y0.x, acc[oo * 4 + 0]);
                acc[oo * 4 + 1] = ffma2(wq, y0.y, acc[oo * 4 + 1]);
                acc[oo * 4 + 2] = ffma2(wq, y1.x, acc[oo * 4 + 2]);
                acc[oo * 4 + 3] = ffma2(wq, y1.y, acc[oo * 4 + 3]);
            }
        }
    }

    /* epilogue: +bias, gelu, store */
    float* ob = out + (b * 128 + out_t * 8) * 9216 + off + px_t * 8;
#pragma unroll
    for (int oo = 0; oo < 8; oo++) {
        float cst = sm[S2_CST + out_t * 8 + oo];
        float* op = ob + oo * 9216;
#pragma unroll
        for (int pp = 0; pp < 4; pp++) {
            float lo, hi; upk2(acc[oo * 4 + pp], lo, hi);
            float2 r;
            r.x = gelu_f(lo + cst);
            r.y = gelu_f(hi + cst);
            *(float2*)(op + pp * 2) = r;
        }
    }
}

extern "C" void kernel_launch(void* const* d_in, const int* in_sizes, int n_in,
                              void* d_out, int out_size)
{
    (void)in_sizes; (void)n_in; (void)out_size;
    const float* x        = (const float*)d_in[0];
    const float* w_reduce = (const float*)d_in[1];
    const float* g_r = (const float*)d_in[2];
    const float* b_r = (const float*)d_in[3];
    const float* m_r = (const float*)d_in[4];
    const float* v_r = (const float*)d_in[5];
    const float* w_span = (const float*)d_in[6];
    const float* b_span = (const float*)d_in[7];
    const float* g_i = (const float*)d_in[8];
    const float* b_i = (const float*)d_in[9];
    const float* m_i = (const float*)d_in[10];
    const float* v_i = (const float*)d_in[11];
    const float* w_conv = (const float*)d_in[12];
    const float* g_c = (const float*)d_in[13];
    const float* b_c = (const float*)d_in[14];
    const float* m_c = (const float*)d_in[15];
    const float* v_c = (const float*)d_in[16];
    const float* w_map = (const float*)d_in[17];
    const float* b_map = (const float*)d_in[18];
    const float* g_m = (const float*)d_in[19];
    const float* b_m = (const float*)d_in[20];
    const float* m_m = (const float*)d_in[21];
    const float* v_m = (const float*)d_in[22];
    float* out = (float*)d_out;

    cudaFuncSetAttribute(k1_involution, cudaFuncAttributeMaxDynamicSharedMemorySize, S1_BYTES);
    cudaFuncSetAttribute(k2_gemm,       cudaFuncAttributeMaxDynamicSharedMemorySize, S2_BYTES);

    dim3 g1(96 / T1W, 96 / T1H, 4);   /* 6 x 12 x 4 = 288 */
    k1_involution<<<g1, 256, S1_BYTES>>>(x, w_reduce, g_r, b_r, m_r, v_r,
                                         w_span, b_span, g_i, b_i, m_i, v_i);
    k2_gemm<<<288, 256, S2_BYTES>>>(x, w_conv, g_c, b_c, m_c, v_c,
                                    w_map, b_map, g_m, b_m, m_m, v_m, out);
}

// round 5
// speedup vs baseline: 1.0369x; 1.0369x over previous
#include <cuda_runtime.h>
#include <math.h>

#define EPSF 1e-5f

typedef unsigned long long u64;

__device__ __forceinline__ u64 pk2(float a, float b) {
    u64 r;
    asm("mov.b64 %0, {%1, %2};" : "=l"(r) : "r"(__float_as_uint(a)), "r"(__float_as_uint(b)));
    return r;
}
__device__ __forceinline__ u64 ffma2(u64 a, u64 b, u64 c) {
    u64 d;
    asm("fma.rn.f32x2 %0, %1, %2, %3;" : "=l"(d) : "l"(a), "l"(b), "l"(c));
    return d;
}
__device__ __forceinline__ void upk2(u64 v, float& lo, float& hi) {
    unsigned int l, h;
    asm("mov.b64 {%0, %1}, %2;" : "=r"(l), "=r"(h) : "l"(v));
    lo = __uint_as_float(l); hi = __uint_as_float(h);
}
__device__ __forceinline__ float gelu_f(float v) {
    return 0.5f * v * (1.0f + erff(v * 0.70710678118654752f));
}

/* intermediate: gelu(bn(involution)) result, [b=4][c=64][hw=9216] */
__device__ float g_x1[4 * 64 * 9216];

/* ================= K1: reduce + span + involution + BN + gelu ================ */
#define T1W 16
#define T1H 8
#define P1W 22
#define P1H 14
#define P1PIX (P1W * P1H)   /* 308 */

#define S1_X    0            /* 64*308 = 19712 */
#define S1_WR   19712        /* [c][16] folded reduce, 1024 */
#define S1_BR   20736        /* 16  */
#define S1_WS   20752        /* [g][r][56] span T, row-padded-8, 3584 */
#define S1_BS   24336        /* [g][56] 224 */
#define S1_SI   24560        /* 64 */
#define S1_SHI  24624        /* 64 */
#define S1_FLOATS 24688
#define S1_BYTES (S1_FLOATS * 4)   /* 98752 B -> 2 CTAs/SM */

__global__ void __launch_bounds__(256, 2)
k1_involution(const float* __restrict__ x,
              const float* __restrict__ w_reduce,
              const float* __restrict__ g_r, const float* __restrict__ b_r,
              const float* __restrict__ m_r, const float* __restrict__ v_r,
              const float* __restrict__ w_span, const float* __restrict__ b_span,
              const float* __restrict__ g_i, const float* __restrict__ b_i,
              const float* __restrict__ m_i, const float* __restrict__ v_i)
{
    extern __shared__ float sm[];
    const int tid = threadIdx.x;
    const int bb  = blockIdx.z;
    const int h0  = blockIdx.y * T1H;
    const int w0  = blockIdx.x * T1W;

    /* halo load: 64ch x 22x14 */
    {
        const int xbase = bb * 64 * 9216;
        for (int i = tid; i < 64 * P1PIX; i += 256) {
            int c  = i / P1PIX;
            int p  = i - c * P1PIX;
            int r  = p / P1W;
            int cl = p - r * P1W;
            int gh = h0 + r - 3;
            int gw = w0 + cl - 3;
            float v = 0.f;
            if ((unsigned)gh < 96u && (unsigned)gw < 96u)
                v = x[xbase + c * 9216 + gh * 96 + gw];
            sm[S1_X + i] = v;
        }
    }
    for (int i = tid; i < 16 * 64; i += 256) {
        int c = i >> 4, r = i & 15;
        float sc = g_r[r] * rsqrtf(v_r[r] + EPSF);
        sm[S1_WR + c * 16 + r] = w_reduce[r * 64 + c] * sc;
    }
    if (tid < 16) {
        float sc = g_r[tid] * rsqrtf(v_r[tid] + EPSF);
        sm[S1_BR + tid] = b_r[tid] - m_r[tid] * sc;
    }
    for (int i = tid; i < 4 * 16 * 56; i += 256) {   /* WS[g][r][56] */
        int g = i / 896, rem = i - g * 896;
        int r = rem / 56, q = rem - r * 56;
        int row = q >> 3, j = q & 7;
        float v = (j < 7) ? w_span[(g * 49 + row * 7 + j) * 16 + r] : 0.f;
        sm[S1_WS + i] = v;
    }
    if (tid < 4 * 56) {
        int g = tid / 56, q = tid - g * 56;
        int row = q >> 3, j = q & 7;
        sm[S1_BS + tid] = (j < 7) ? b_span[g * 49 + row * 7 + j] : 0.f;
    }
    if (tid < 64) {
        float sc = g_i[tid] * rsqrtf(v_i[tid] + EPSF);
        sm[S1_SI + tid]  = sc;
        sm[S1_SHI + tid] = b_i[tid] - m_i[tid] * sc;
    }
    __syncthreads();

    const int px_id = tid & 127;
    const int gp    = tid >> 7;          /* 0/1 -> groups {0,1} or {2,3} */
    const int px    = px_id & 15;
    const int py    = px_id >> 4;
    const int cen   = (py + 3) * P1W + (px + 3);

    /* t = relu(reduce + BN), packed f32x2 */
    u64 t2[8];
    {
        const u64* br2 = (const u64*)(sm + S1_BR);
#pragma unroll
        for (int q = 0; q < 8; q++) t2[q] = br2[q];
    }
#pragma unroll 8
    for (int c = 0; c < 64; c++) {
        float xv = sm[S1_X + c * P1PIX + cen];
        u64 xv2 = pk2(xv, xv);
        const ulonglong2* w2 = (const ulonglong2*)(sm + S1_WR + c * 16);
#pragma unroll
        for (int q = 0; q < 4; q++) {
            ulonglong2 w = w2[q];
            t2[2 * q + 0] = ffma2(w.x, xv2, t2[2 * q + 0]);
            t2[2 * q + 1] = ffma2(w.y, xv2, t2[2 * q + 1]);
        }
    }
    float tt[16];
#pragma unroll
    for (int q = 0; q < 8; q++) {
        float lo, hi; upk2(t2[q], lo, hi);
        tt[2 * q] = fmaxf(lo, 0.f); tt[2 * q + 1] = fmaxf(hi, 0.f);
    }

    const int obase = bb * 64 * 9216 + (h0 + py) * 96 + (w0 + px);

#pragma unroll 1
    for (int gi = 0; gi < 2; gi++) {
        const int g = gp * 2 + gi;
        /* kern[56] (row-padded 8), accumulated packed */
        u64 kq[28];
        {
            const u64* b2 = (const u64*)(sm + S1_BS + g * 56);
#pragma unroll
            for (int q = 0; q < 28; q++) kq[q] = b2[q];
        }
#pragma unroll 4
        for (int r = 0; r < 16; r++) {
            u64 tv2 = pk2(tt[r], tt[r]);
            const ulonglong2* w2 = (const ulonglong2*)(sm + S1_WS + (g * 16 + r) * 56);
#pragma unroll
            for (int q = 0; q < 14; q++) {
                ulonglong2 w = w2[q];
                kq[2 * q + 0] = ffma2(w.x, tv2, kq[2 * q + 0]);
                kq[2 * q + 1] = ffma2(w.y, tv2, kq[2 * q + 1]);
            }
        }
        float kkv[56];
#pragma unroll
        for (int q = 0; q < 28; q++) upk2(kq[q], kkv[2 * q], kkv[2 * q + 1]);

        /* involution over 16 channels of this group */
#pragma unroll 1
        for (int ci = 0; ci < 16; ci++) {
            const int c = g * 16 + ci;
            const float* xb = sm + S1_X + c * P1PIX + py * P1W + px;
            float a[7];
#pragma unroll
            for (int i = 0; i < 7; i++) {
                float ai = kkv[i * 8] * xb[i * P1W];
#pragma unroll
                for (int j = 1; j < 7; j++)
                    ai = fmaf(kkv[i * 8 + j], xb[i * P1W + j], ai);
                a[i] = ai;
            }
            float acc = ((a[0] + a[1]) + (a[2] + a[3])) + ((a[4] + a[5]) + a[6]);
            float v = fmaf(acc, sm[S1_SI + c], sm[S1_SHI + c]);
            g_x1[obase + c * 9216] = gelu_f(v);
        }
    }
}

/* ================= K2: fused 128x128 GEMM + bias + gelu ================ */
/* C[128 out][36864 px] = W2T . [x1 | x], tile 128 px x 128 out per CTA.
   Y staged through SMEM in double-buffered k-chunks of 16.               */
#define KC 16
#define S2_W   0        /* W2T[k=128][o=128] 16384 floats */
#define S2_CST 16384    /* 128 */
#define S2_Y   16512    /* [2][KC][128] = 4096 floats */
#define S2_FLOATS 20608
#define S2_BYTES (S2_FLOATS * 4)   /* 82432 B -> 2 CTAs/SM */

__global__ void __launch_bounds__(256, 2)
k2_gemm(const float* __restrict__ x,
        const float* __restrict__ w_conv,
        const float* __restrict__ g_c, const float* __restrict__ b_c,
        const float* __restrict__ m_c, const float* __restrict__ v_c,
        const float* __restrict__ w_map, const float* __restrict__ b_map,
        const float* __restrict__ g_m, const float* __restrict__ b_m,
        const float* __restrict__ m_m, const float* __restrict__ v_m,
        float* __restrict__ out)
{
    extern __shared__ float sm[];
    const int tid = threadIdx.x;

    /* build W2T[k][o] with BN folded */
    for (int i = tid; i < 16384; i += 256) {
        int k = i >> 7, o = i & 127;
        float v;
        if (k < 64) v = w_conv[o * 64 + k]        * (g_c[o] * rsqrtf(v_c[o] + EPSF));
        else        v = w_map [o * 64 + (k - 64)] * (g_m[o] * rsqrtf(v_m[o] + EPSF));
        sm[S2_W + i] = v;
    }
    if (tid < 128) {
        float sc_c = g_c[tid] * rsqrtf(v_c[tid] + EPSF);
        float sc_m = g_m[tid] * rsqrtf(v_m[tid] + EPSF);
        sm[S2_CST + tid] = (b_c[tid] - m_c[tid] * sc_c)
                         + sc_m * b_map[tid]
                         + (b_m[tid] - m_m[tid] * sc_m);
    }

    const int P0  = blockIdx.x * 128;        /* global pixel base */
    const int b   = P0 / 9216;
    const int off = P0 - b * 9216;
    const int px_t  = tid & 15;              /* 8 px each  */
    const int out_t = tid >> 4;              /* 8 out each */

    /* chunk-load geometry: thread loads row ldr (of KC), cols ldc..ldc+8 */
    const int ldr = tid >> 4;
    const int ldc = (tid & 15) * 8;
    const float* x1base = g_x1 + (b * 64) * 9216 + off;
    const float* xbase  = x    + (b * 64) * 9216 + off;

    /* prologue: load chunk 0 (k = 0..15, from g_x1) */
    float4 v0 = *(const float4*)(x1base + ldr * 9216 + ldc);
    float4 v1 = *(const float4*)(x1base + ldr * 9216 + ldc + 4);
    *(float4*)(sm + S2_Y + ldr * 128 + ldc)     = v0;
    *(float4*)(sm + S2_Y + ldr * 128 + ldc + 4) = v1;
    __syncthreads();

    u64 acc[32];                             /* [oo=8][pp=4] px pairs */
#pragma unroll
    for (int q = 0; q < 32; q++) acc[q] = 0ULL;

#pragma unroll 1
    for (int ch = 0; ch < 8; ch++) {
        /* issue loads for next chunk */
        if (ch < 7) {
            int k0n = (ch + 1) * KC;
            const float* src = (k0n < 64) ? (x1base + k0n * 9216)
                                          : (xbase + (k0n - 64) * 9216);
            v0 = *(const float4*)(src + ldr * 9216 + ldc);
            v1 = *(const float4*)(src + ldr * 9216 + ldc + 4);
        }

        /* compute on current chunk */
        const float* yb = sm + S2_Y + (ch & 1) * (KC * 128) + px_t * 8;
        const float* wb = sm + S2_W + ch * KC * 128 + out_t * 8;
#pragma unroll 4
        for (int kk = 0; kk < KC; kk++) {
            const ulonglong2* yp = (const ulonglong2*)(yb + kk * 128);
            ulonglong2 y0 = yp[0];
            ulonglong2 y1 = yp[1];
            const float4* wp = (const float4*)(wb + kk * 128);
            float4 w0 = wp[0];
            float4 w1 = wp[1];
            float wv[8] = {w0.x, w0.y, w0.z, w0.w, w1.x, w1.y, w1.z, w1.w};
#pragma unroll
            for (int oo = 0; oo < 8; oo++) {
                u64 wq = pk2(wv[oo], wv[oo]);
                acc[oo * 4 + 0] = ffma2(wq, y0.x, acc[oo * 4 + 0]);
                acc[oo * 4 + 1] = ffma2(wq, y0.y, acc[oo * 4 + 1]);
                acc[oo * 4 + 2] = ffma2(wq, y1.x, acc[oo * 4 + 2]);
                acc[oo * 4 + 3] = ffma2(wq, y1.y, acc[oo * 4 + 3]);
            }
        }

        /* commit next chunk to the other buffer */
        if (ch < 7) {
            float* dst = sm + S2_Y + ((ch + 1) & 1) * (KC * 128) + ldr * 128 + ldc;
            *(float4*)(dst)     = v0;
            *(float4*)(dst + 4) = v1;
        }
        __syncthreads();
    }

    /* epilogue: +bias, gelu, store as float4 pairs */
    float* ob = out + (b * 128 + out_t * 8) * 9216 + off + px_t * 8;
#pragma unroll
    for (int oo = 0; oo < 8; oo++) {
        float cst = sm[S2_CST + out_t * 8 + oo];
        float r[8];
#pragma unroll
        for (int pp = 0; pp < 4; pp++) {
            float lo, hi; upk2(acc[oo * 4 + pp], lo, hi);
            r[2 * pp]     = gelu_f(lo + cst);
            r[2 * pp + 1] = gelu_f(hi + cst);
        }
        float* op = ob + oo * 9216;
        *(float4*)(op)     = make_float4(r[0], r[1], r[2], r[3]);
        *(float4*)(op + 4) = make_float4(r[4], r[5], r[6], r[7]);
    }
}

extern "C" void kernel_launch(void* const* d_in, const int* in_sizes, int n_in,
                              void* d_out, int out_size)
{
    (void)in_sizes; (void)n_in; (void)out_size;
    const float* x        = (const float*)d_in[0];
    const float* w_reduce = (const float*)d_in[1];
    const float* g_r = (const float*)d_in[2];
    const float* b_r = (const float*)d_in[3];
    const float* m_r = (const float*)d_in[4];
    const float* v_r = (const float*)d_in[5];
    const float* w_span = (const float*)d_in[6];
    const float* b_span = (const float*)d_in[7];
    const float* g_i = (const float*)d_in[8];
    const float* b_i = (const float*)d_in[9];
    const float* m_i = (const float*)d_in[10];
    const float* v_i = (const float*)d_in[11];
    const float* w_conv = (const float*)d_in[12];
    const float* g_c = (const float*)d_in[13];
    const float* b_c = (const float*)d_in[14];
    const float* m_c = (const float*)d_in[15];
    const float* v_c = (const float*)d_in[16];
    const float* w_map = (const float*)d_in[17];
    const float* b_map = (const float*)d_in[18];
    const float* g_m = (const float*)d_in[19];
    const float* b_m = (const float*)d_in[20];
    const float* m_m = (const float*)d_in[21];
    const float* v_m = (const float*)d_in[22];
    float* out = (float*)d_out;

    cudaFuncSetAttribute(k1_involution, cudaFuncAttributeMaxDynamicSharedMemorySize, S1_BYTES);
    cudaFuncSetAttribute(k2_gemm,       cudaFuncAttributeMaxDynamicSharedMemorySize, S2_BYTES);

    dim3 g1(96 / T1W, 96 / T1H, 4);   /* 6 x 12 x 4 = 288 */
    k1_involution<<<g1, 256, S1_BYTES>>>(x, w_reduce, g_r, b_r, m_r, v_r,
                                         w_span, b_span, g_i, b_i, m_i, v_i);
    k2_gemm<<<288, 256, S2_BYTES>>>(x, w_conv, g_c, b_c, m_c, v_c,
                                    w_map, b_map, g_m, b_m, m_m, v_m, out);
}

// round 6
// speedup vs baseline: 1.3544x; 1.3063x over previous
#include <cuda_runtime.h>
#include <math.h>

#define EPSF 1e-5f

typedef unsigned long long u64;
typedef unsigned int u32;

__device__ __forceinline__ u64 pk2(float a, float b) {
    u64 r;
    asm("mov.b64 %0, {%1, %2};" : "=l"(r) : "r"(__float_as_uint(a)), "r"(__float_as_uint(b)));
    return r;
}
__device__ __forceinline__ u64 ffma2(u64 a, u64 b, u64 c) {
    u64 d;
    asm("fma.rn.f32x2 %0, %1, %2, %3;" : "=l"(d) : "l"(a), "l"(b), "l"(c));
    return d;
}
__device__ __forceinline__ void upk2(u64 v, float& lo, float& hi) {
    unsigned int l, h;
    asm("mov.b64 {%0, %1}, %2;" : "=r"(l), "=r"(h) : "l"(v));
    lo = __uint_as_float(l); hi = __uint_as_float(h);
}
__device__ __forceinline__ float gelu_f(float v) {
    return 0.5f * v * (1.0f + erff(v * 0.70710678118654752f));
}
__device__ __forceinline__ u32 tf32c(float f) {
    u32 r;
    asm("cvt.rna.tf32.f32 %0, %1;" : "=r"(r) : "f"(f));
    return r;
}

/* intermediate: gelu(bn(involution)) result, [b=4][c=64][hw=9216] */
__device__ float g_x1[4 * 64 * 9216];

/* ================= K1: reduce + span + involution + BN + gelu ================ */
#define T1W 16
#define T1H 8
#define P1W 22
#define P1H 14
#define P1PIX (P1W * P1H)   /* 308 */

#define S1_X    0            /* 64*308 = 19712 */
#define S1_WR   19712        /* [c][16] folded reduce, 1024 */
#define S1_BR   20736        /* 16  */
#define S1_WS   20752        /* [g][r][56] span T, row-padded-8, 3584 */
#define S1_BS   24336        /* [g][56] 224 */
#define S1_SI   24560        /* 64 */
#define S1_SHI  24624        /* 64 */
#define S1_FLOATS 24688
#define S1_BYTES (S1_FLOATS * 4)   /* 98752 B -> 2 CTAs/SM */

__global__ void __launch_bounds__(256, 2)
k1_involution(const float* __restrict__ x,
              const float* __restrict__ w_reduce,
              const float* __restrict__ g_r, const float* __restrict__ b_r,
              const float* __restrict__ m_r, const float* __restrict__ v_r,
              const float* __restrict__ w_span, const float* __restrict__ b_span,
              const float* __restrict__ g_i, const float* __restrict__ b_i,
              const float* __restrict__ m_i, const float* __restrict__ v_i)
{
    extern __shared__ float sm[];
    const int tid = threadIdx.x;
    const int bb  = blockIdx.z;
    const int h0  = blockIdx.y * T1H;
    const int w0  = blockIdx.x * T1W;

    {
        const int xbase = bb * 64 * 9216;
        for (int i = tid; i < 64 * P1PIX; i += 256) {
            int c  = i / P1PIX;
            int p  = i - c * P1PIX;
            int r  = p / P1W;
            int cl = p - r * P1W;
            int gh = h0 + r - 3;
            int gw = w0 + cl - 3;
            float v = 0.f;
            if ((unsigned)gh < 96u && (unsigned)gw < 96u)
                v = x[xbase + c * 9216 + gh * 96 + gw];
            sm[S1_X + i] = v;
        }
    }
    for (int i = tid; i < 16 * 64; i += 256) {
        int c = i >> 4, r = i & 15;
        float sc = g_r[r] * rsqrtf(v_r[r] + EPSF);
        sm[S1_WR + c * 16 + r] = w_reduce[r * 64 + c] * sc;
    }
    if (tid < 16) {
        float sc = g_r[tid] * rsqrtf(v_r[tid] + EPSF);
        sm[S1_BR + tid] = b_r[tid] - m_r[tid] * sc;
    }
    for (int i = tid; i < 4 * 16 * 56; i += 256) {   /* WS[g][r][56] */
        int g = i / 896, rem = i - g * 896;
        int r = rem / 56, q = rem - r * 56;
        int row = q >> 3, j = q & 7;
        float v = (j < 7) ? w_span[(g * 49 + row * 7 + j) * 16 + r] : 0.f;
        sm[S1_WS + i] = v;
    }
    if (tid < 4 * 56) {
        int g = tid / 56, q = tid - g * 56;
        int row = q >> 3, j = q & 7;
        sm[S1_BS + tid] = (j < 7) ? b_span[g * 49 + row * 7 + j] : 0.f;
    }
    if (tid < 64) {
        float sc = g_i[tid] * rsqrtf(v_i[tid] + EPSF);
        sm[S1_SI + tid]  = sc;
        sm[S1_SHI + tid] = b_i[tid] - m_i[tid] * sc;
    }
    __syncthreads();

    const int px_id = tid & 127;
    const int gp    = tid >> 7;
    const int px    = px_id & 15;
    const int py    = px_id >> 4;
    const int cen   = (py + 3) * P1W + (px + 3);

    u64 t2[8];
    {
        const u64* br2 = (const u64*)(sm + S1_BR);
#pragma unroll
        for (int q = 0; q < 8; q++) t2[q] = br2[q];
    }
#pragma unroll 8
    for (int c = 0; c < 64; c++) {
        float xv = sm[S1_X + c * P1PIX + cen];
        u64 xv2 = pk2(xv, xv);
        const ulonglong2* w2 = (const ulonglong2*)(sm + S1_WR + c * 16);
#pragma unroll
        for (int q = 0; q < 4; q++) {
            ulonglong2 w = w2[q];
            t2[2 * q + 0] = ffma2(w.x, xv2, t2[2 * q + 0]);
            t2[2 * q + 1] = ffma2(w.y, xv2, t2[2 * q + 1]);
        }
    }
    float tt[16];
#pragma unroll
    for (int q = 0; q < 8; q++) {
        float lo, hi; upk2(t2[q], lo, hi);
        tt[2 * q] = fmaxf(lo, 0.f); tt[2 * q + 1] = fmaxf(hi, 0.f);
    }

    const int obase = bb * 64 * 9216 + (h0 + py) * 96 + (w0 + px);

#pragma unroll 1
    for (int gi = 0; gi < 2; gi++) {
        const int g = gp * 2 + gi;
        u64 kq[28];
        {
            const u64* b2 = (const u64*)(sm + S1_BS + g * 56);
#pragma unroll
            for (int q = 0; q < 28; q++) kq[q] = b2[q];
        }
#pragma unroll 4
        for (int r = 0; r < 16; r++) {
            u64 tv2 = pk2(tt[r], tt[r]);
            const ulonglong2* w2 = (const ulonglong2*)(sm + S1_WS + (g * 16 + r) * 56);
#pragma unroll
            for (int q = 0; q < 14; q++) {
                ulonglong2 w = w2[q];
                kq[2 * q + 0] = ffma2(w.x, tv2, kq[2 * q + 0]);
                kq[2 * q + 1] = ffma2(w.y, tv2, kq[2 * q + 1]);
            }
        }
        float kkv[56];
#pragma unroll
        for (int q = 0; q < 28; q++) upk2(kq[q], kkv[2 * q], kkv[2 * q + 1]);

#pragma unroll 1
        for (int ci = 0; ci < 16; ci++) {
            const int c = g * 16 + ci;
            const float* xb = sm + S1_X + c * P1PIX + py * P1W + px;
            float a[7];
#pragma unroll
            for (int i = 0; i < 7; i++) {
                float ai = kkv[i * 8] * xb[i * P1W];
#pragma unroll
                for (int j = 1; j < 7; j++)
                    ai = fmaf(kkv[i * 8 + j], xb[i * P1W + j], ai);
                a[i] = ai;
            }
            float acc = ((a[0] + a[1]) + (a[2] + a[3])) + ((a[4] + a[5]) + a[6]);
            float v = fmaf(acc, sm[S1_SI + c], sm[S1_SHI + c]);
            g_x1[obase + c * 9216] = gelu_f(v);
        }
    }
}

/* ================= K2: tf32 tensor-core GEMM + bias + gelu ================ */
/* out[128 o][36864 px] = W2[o][k=128] . Y[k][px], Y = [x1 | x].
   Per CTA: 128 px x all 128 out. 8 warps, each warp m16 x n128.
   W in SMEM tf32 [o][132-pad]; Y staged tf32 per 16-k chunk, double buffered. */
#define S2_W    0            /* 128*132 = 16896 (tf32 as u32) */
#define S2_CST  16896        /* 128 */
#define S2_Y    17024        /* [2][16][132] = 4224 */
#define S2_FLOATS 21248
#define S2_BYTES (S2_FLOATS * 4)   /* 84992 B -> 2 CTAs/SM */

__global__ void __launch_bounds__(256, 2)
k2_mma(const float* __restrict__ x,
       const float* __restrict__ w_conv,
       const float* __restrict__ g_c, const float* __restrict__ b_c,
       const float* __restrict__ m_c, const float* __restrict__ v_c,
       const float* __restrict__ w_map, const float* __restrict__ b_map,
       const float* __restrict__ g_m, const float* __restrict__ b_m,
       const float* __restrict__ m_m, const float* __restrict__ v_m,
       float* __restrict__ out)
{
    extern __shared__ float smf[];
    u32* smu = (u32*)smf;
    const int tid = threadIdx.x;

    /* fold BN into W2, convert to tf32: W[o][k] @ pad 132 */
    for (int i = tid; i < 16384; i += 256) {
        int o = i >> 7, k = i & 127;
        float v;
        if (k < 64) v = w_conv[o * 64 + k]        * (g_c[o] * rsqrtf(v_c[o] + EPSF));
        else        v = w_map [o * 64 + (k - 64)] * (g_m[o] * rsqrtf(v_m[o] + EPSF));
        smu[S2_W + o * 132 + k] = tf32c(v);
    }
    if (tid < 128) {
        float sc_c = g_c[tid] * rsqrtf(v_c[tid] + EPSF);
        float sc_m = g_m[tid] * rsqrtf(v_m[tid] + EPSF);
        smf[S2_CST + tid] = (b_c[tid] - m_c[tid] * sc_c)
                          + sc_m * b_map[tid]
                          + (b_m[tid] - m_m[tid] * sc_m);
    }

    const int P0  = blockIdx.x * 128;
    const int b   = P0 / 9216;
    const int off = P0 - b * 9216;

    const int ldr = tid >> 4;            /* k row in chunk, 0..15 */
    const int ldc = (tid & 15) * 8;      /* px col, step 8 */
    const float* x1base = g_x1 + (b * 64) * 9216 + off;
    const float* xbase  = x    + (b * 64) * 9216 + off;

    /* stage chunk 0 (k=0..15 from g_x1) */
    float4 v0 = *(const float4*)(x1base + ldr * 9216 + ldc);
    float4 v1 = *(const float4*)(x1base + ldr * 9216 + ldc + 4);
    {
        u32* yd = smu + S2_Y + ldr * 132 + ldc;
        yd[0] = tf32c(v0.x); yd[1] = tf32c(v0.y); yd[2] = tf32c(v0.z); yd[3] = tf32c(v0.w);
        yd[4] = tf32c(v1.x); yd[5] = tf32c(v1.y); yd[6] = tf32c(v1.z); yd[7] = tf32c(v1.w);
    }
    __syncthreads();

    const int lane = tid & 31;
    const int gid  = lane >> 2;          /* group 0..7 */
    const int tig  = lane & 3;           /* 0..3 */
    const int m0   = (tid >> 5) * 16;    /* warp's out-row base */

    float c[16][4];
#pragma unroll
    for (int nt = 0; nt < 16; nt++)
#pragma unroll
        for (int q = 0; q < 4; q++) c[nt][q] = 0.f;

#pragma unroll 1
    for (int ch = 0; ch < 8; ch++) {
        if (ch < 7) {
            int kg = (ch + 1) * 16 + ldr;
            const float* src = (kg < 64) ? (x1base + kg * 9216)
                                         : (xbase + (kg - 64) * 9216);
            v0 = *(const float4*)(src + ldc);
            v1 = *(const float4*)(src + ldc + 4);
        }

        const u32* Yb = smu + S2_Y + (ch & 1) * 2112;
#pragma unroll
        for (int ks = 0; ks < 2; ks++) {
            const int kg = ch * 16 + ks * 8;
            u32 a0 = smu[S2_W + (m0 + gid) * 132 + kg + tig];
            u32 a2 = smu[S2_W + (m0 + gid) * 132 + kg + tig + 4];
            u32 a1 = smu[S2_W + (m0 + gid + 8) * 132 + kg + tig];
            u32 a3 = smu[S2_W + (m0 + gid + 8) * 132 + kg + tig + 4];
            const u32* bb = Yb + (ks * 8 + tig) * 132 + gid;
#pragma unroll
            for (int nt = 0; nt < 16; nt++) {
                u32 b0 = bb[nt * 8];
                u32 b1 = bb[nt * 8 + 4 * 132];
                asm volatile(
                    "mma.sync.aligned.m16n8k8.row.col.f32.tf32.tf32.f32 "
                    "{%0,%1,%2,%3}, {%4,%5,%6,%7}, {%8,%9}, {%0,%1,%2,%3};"
                    : "+f"(c[nt][0]), "+f"(c[nt][1]), "+f"(c[nt][2]), "+f"(c[nt][3])
                    : "r"(a0), "r"(a1), "r"(a2), "r"(a3), "r"(b0), "r"(b1));
            }
        }

        if (ch < 7) {
            u32* yd = smu + S2_Y + ((ch + 1) & 1) * 2112 + ldr * 132 + ldc;
            yd[0] = tf32c(v0.x); yd[1] = tf32c(v0.y); yd[2] = tf32c(v0.z); yd[3] = tf32c(v0.w);
            yd[4] = tf32c(v1.x); yd[5] = tf32c(v1.y); yd[6] = tf32c(v1.z); yd[7] = tf32c(v1.w);
        }
        __syncthreads();
    }

    /* epilogue: bias + gelu, direct STG.64 */
    float* ob = out + (b * 128) * 9216 + off;
    const int o0 = m0 + gid;
    const float cst0 = smf[S2_CST + o0];
    const float cst1 = smf[S2_CST + o0 + 8];
#pragma unroll
    for (int nt = 0; nt < 16; nt++) {
        int pxl = nt * 8 + tig * 2;
        float2 r0, r1;
        r0.x = gelu_f(c[nt][0] + cst0);
        r0.y = gelu_f(c[nt][1] + cst0);
        r1.x = gelu_f(c[nt][2] + cst1);
        r1.y = gelu_f(c[nt][3] + cst1);
        *(float2*)(ob + o0 * 9216 + pxl)       = r0;
        *(float2*)(ob + (o0 + 8) * 9216 + pxl) = r1;
    }
}

extern "C" void kernel_launch(void* const* d_in, const int* in_sizes, int n_in,
                              void* d_out, int out_size)
{
    (void)in_sizes; (void)n_in; (void)out_size;
    const float* x        = (const float*)d_in[0];
    const float* w_reduce = (const float*)d_in[1];
    const float* g_r = (const float*)d_in[2];
    const float* b_r = (const float*)d_in[3];
    const float* m_r = (const float*)d_in[4];
    const float* v_r = (const float*)d_in[5];
    const float* w_span = (const float*)d_in[6];
    const float* b_span = (const float*)d_in[7];
    const float* g_i = (const float*)d_in[8];
    const float* b_i = (const float*)d_in[9];
    const float* m_i = (const float*)d_in[10];
    const float* v_i = (const float*)d_in[11];
    const float* w_conv = (const float*)d_in[12];
    const float* g_c = (const float*)d_in[13];
    const float* b_c = (const float*)d_in[14];
    const float* m_c = (const float*)d_in[15];
    const float* v_c = (const float*)d_in[16];
    const float* w_map = (const float*)d_in[17];
    const float* b_map = (const float*)d_in[18];
    const float* g_m = (const float*)d_in[19];
    const float* b_m = (const float*)d_in[20];
    const float* m_m = (const float*)d_in[21];
    const float* v_m = (const float*)d_in[22];
    float* out = (float*)d_out;

    cudaFuncSetAttribute(k1_involution, cudaFuncAttributeMaxDynamicSharedMemorySize, S1_BYTES);
    cudaFuncSetAttribute(k2_mma,        cudaFuncAttributeMaxDynamicSharedMemorySize, S2_BYTES);

    dim3 g1(96 / T1W, 96 / T1H, 4);   /* 6 x 12 x 4 = 288 */
    k1_involution<<<g1, 256, S1_BYTES>>>(x, w_reduce, g_r, b_r, m_r, v_r,
                                         w_span, b_span, g_i, b_i, m_i, v_i);
    k2_mma<<<288, 256, S2_BYTES>>>(x, w_conv, g_c, b_c, m_c, v_c,
                                   w_map, b_map, g_m, b_m, m_m, v_m, out);
}